// round 5
// baseline (speedup 1.0000x reference)
#include <cuda_runtime.h>
#include <math.h>
#include <stdint.h>

// Problem constants (match reference)
#define N_INPUTS 2048
#define UNITS    2048
#define L        8
#define FANIN    4096
#define TOTAL    (N_INPUTS + L * UNITS)   // 18432

// GEMV decomposition
#define KSPLIT   256
#define KCHUNK   (FANIN / KSPLIT)         // 16 rows per block
#define TPB      256                      // threads per gemv block
#define U_HALF   1024                     // units per block (1 float4/thread)
#define U_TILES  (UNITS / U_HALF)         // 2

#define TILE_FLOATS (KCHUNK * U_HALF)     // 16384 floats = 64 KB
#define SMEM_BYTES  (TILE_FLOATS * 4 + KCHUNK * 4)

// Scratch (device globals: allocation-free per harness rules)
__device__ float g_state[TOTAL];                 // shared "outputs" vector
__device__ float g_partial[KSPLIT * UNITS];      // split-K partial sums (2 MB)

__device__ __forceinline__ uint32_t smem_u32(const void* p) {
    uint32_t a;
    asm("{ .reg .u64 t; cvta.to.shared.u64 t, %1; cvt.u32.u64 %0, t; }"
        : "=r"(a) : "l"(p));
    return a;
}

__device__ __forceinline__ void cp_async16(uint32_t dst_smem, const void* src_gmem) {
    asm volatile("cp.async.cg.shared.global [%0], [%1], 16;"
                 :: "r"(dst_smem), "l"(src_gmem));
}

// Zero the state vector and write x into segment 0.
__global__ void init_kernel(const float* __restrict__ x) {
    int i = blockIdx.x * blockDim.x + threadIdx.x;
    if (i < TOTAL) {
        g_state[i] = (i < N_INPUTS) ? x[i] : 0.0f;
    }
}

// One layer's GEMV partial via cp.async-staged W tiles.
// Block (ub, kb): units [ub*1024, ub*1024+1024), rows [kb*16, kb*16+16).
// Each thread issues 16 independent 16B cp.asyncs (its float4 column in each
// of the 16 rows) -> the whole 64KB tile is in flight without any register
// pressure (LDGSTS has no depth cap). 3 resident blocks/SM keep ~192KB/SM
// outstanding, enough to saturate HBM/LTS instead of the ~3.3TB/s register-
// limited LDG plateau.
__global__ __launch_bounds__(TPB) void gemv_partial_kernel(
    const float* __restrict__ W,      // [FANIN, UNITS] for this layer
    const int*   __restrict__ inds)   // [FANIN] for this layer
{
    extern __shared__ __align__(16) float smem[];
    float* tile = smem;                      // [KCHUNK][U_HALF]
    float* gs   = smem + TILE_FLOATS;        // [KCHUNK]

    const int tid = threadIdx.x;
    const int ub  = blockIdx.x;
    const int k0  = blockIdx.y * KCHUNK;
    const int ucol = ub * U_HALF + tid * 4;  // this thread's unit column (4 units)

    // Gather the 16 input values for this K-chunk.
    if (tid < KCHUNK) {
        gs[tid] = g_state[inds[k0 + tid]];
    }

    // Stage the 64KB W tile: 16 independent 16B async copies per thread.
    const uint32_t tile_s = smem_u32(tile) + (uint32_t)tid * 16u;
    const float* Wg = W + (size_t)k0 * UNITS + ucol;
    #pragma unroll
    for (int k = 0; k < KCHUNK; ++k) {
        cp_async16(tile_s + (uint32_t)k * (U_HALF * 4u), Wg + (size_t)k * UNITS);
    }
    asm volatile("cp.async.commit_group;");
    asm volatile("cp.async.wait_group 0;");
    __syncthreads();

    const float4* tile4 = reinterpret_cast<const float4*>(tile);
    float4 acc = make_float4(0.f, 0.f, 0.f, 0.f);
    #pragma unroll
    for (int k = 0; k < KCHUNK; ++k) {
        const float  s = gs[k];
        const float4 w = tile4[k * (U_HALF / 4) + tid];
        acc.x = fmaf(s, w.x, acc.x);
        acc.y = fmaf(s, w.y, acc.y);
        acc.z = fmaf(s, w.z, acc.z);
        acc.w = fmaf(s, w.w, acc.w);
    }

    float4* pp = reinterpret_cast<float4*>(g_partial + (size_t)blockIdx.y * UNITS + ucol);
    *pp = acc;
}

// Warp-per-unit reduction of the KSPLIT partials + bias + tanh.
// Block = 256 threads = 8 warps -> 8 units per block; grid = UNITS/8 = 256.
__global__ __launch_bounds__(256) void finalize_kernel(
    const float* __restrict__ b,
    int seg_offset,
    float* __restrict__ out /* may be null */)
{
    const int warp = threadIdx.x >> 5;
    const int lane = threadIdx.x & 31;
    const int u    = blockIdx.x * 8 + warp;

    float acc = 0.0f;
    #pragma unroll
    for (int s = lane; s < KSPLIT; s += 32) {
        acc += g_partial[(size_t)s * UNITS + u];
    }
    #pragma unroll
    for (int off = 16; off > 0; off >>= 1) {
        acc += __shfl_xor_sync(0xFFFFFFFFu, acc, off);
    }

    if (lane == 0) {
        const float v = tanhf(acc + b[u]);
        g_state[seg_offset + u] = v;
        if (out) out[u] = v;
    }
}

extern "C" void kernel_launch(void* const* d_in, const int* in_sizes, int n_in,
                              void* d_out, int out_size) {
    const float* x         = (const float*)d_in[0];  // [2048] f32
    const int*   node_inds = (const int*)  d_in[1];  // [L, FANIN] i32
    const float* Ws        = (const float*)d_in[2];  // [L, FANIN, UNITS] f32
    const float* bs        = (const float*)d_in[3];  // [L, UNITS] f32
    float*       out       = (float*)d_out;          // [2048] f32

    // Idempotent; needed for >48KB dynamic smem. Not an allocation.
    cudaFuncSetAttribute(gemv_partial_kernel,
                         cudaFuncAttributeMaxDynamicSharedMemorySize, SMEM_BYTES);

    init_kernel<<<(TOTAL + 255) / 256, 256>>>(x);

    for (int i = 0; i < L; ++i) {
        const float* Wi = Ws + (size_t)i * FANIN * UNITS;
        const int*   Ii = node_inds + i * FANIN;
        const float* bi = bs + i * UNITS;

        dim3 grid(U_TILES, KSPLIT);                  // 2 x 256 = 512 blocks
        gemv_partial_kernel<<<grid, TPB, SMEM_BYTES>>>(Wi, Ii);

        const int seg = (i + 1) * UNITS;             // segment 8 exists; harmless
        finalize_kernel<<<UNITS / 8, 256>>>(bi, seg, (i == L - 1) ? out : nullptr);
    }
}

// round 6
// speedup vs baseline: 1.2485x; 1.2485x over previous
#include <cuda_runtime.h>
#include <math.h>

// Problem constants (match reference)
#define N_INPUTS 2048
#define UNITS    2048
#define L        8
#define FANIN    4096
#define TOTAL    (N_INPUTS + L * UNITS)   // 18432

// GEMV decomposition
#define KSPLIT   256
#define KCHUNK   (FANIN / KSPLIT)         // 16 rows per block
#define TPB      256                      // threads per gemv block
// Each thread owns TWO float4 unit-columns: u = tid*4 and u = 4096+tid*4... (tid*4 and 1024*? see below)

// Scratch (device globals: allocation-free per harness rules)
__device__ float g_state[TOTAL];                 // shared "outputs" vector
__device__ float g_partial[KSPLIT * UNITS];      // split-K partial sums (2 MB)

// Zero the state vector and write x into segment 0. Segments 1..8 MUST be
// re-zeroed every call: the zero-skip below relies on exact zeros, and
// g_state persists across graph replays.
__global__ void init_kernel(const float* __restrict__ x) {
    int i = blockIdx.x * blockDim.x + threadIdx.x;
    if (i < TOTAL) {
        g_state[i] = (i < N_INPUTS) ? x[i] : 0.0f;
    }
}

// One layer's GEMV partial with ZERO-SKIP.
// Block kb handles rows [kb*16, kb*16+16) and ALL 2048 units.
// Thread tid owns unit columns [4*tid, 4*tid+3] and [1024+4*tid, 1024+4*tid+3]
// (two independent float4 loads per live row -> 2x per-thread MLP).
// Rows whose gathered input is exactly 0.0f (segments not yet written) are
// compacted away: neither their W bytes are loaded nor their FMAs issued.
// Expected live fraction at layer i is (i+1)/9 -> 2x total DRAM traffic cut.
__global__ __launch_bounds__(TPB) void gemv_partial_kernel(
    const float* __restrict__ W,      // [FANIN, UNITS] for this layer
    const int*   __restrict__ inds)   // [FANIN] for this layer
{
    __shared__ float gsc[KCHUNK];     // compacted gathered values
    __shared__ int   liv[KCHUNK];     // compacted live row indices (0..15)
    __shared__ int   nliv;

    const int tid = threadIdx.x;
    const int k0  = blockIdx.x * KCHUNK;

    if (tid == 0) nliv = 0;
    __syncthreads();

    if (tid < KCHUNK) {
        const float v = g_state[inds[k0 + tid]];
        if (v != 0.0f) {
            const int j = atomicAdd(&nliv, 1);
            liv[j] = tid;
            gsc[j] = v;
        }
    }
    __syncthreads();

    const int n = nliv;

    // float4 view: row stride = UNITS/4 = 512 float4s.
    const float4* W4 = reinterpret_cast<const float4*>(W) + (size_t)k0 * 512 + tid;

    float4 a0 = make_float4(0.f, 0.f, 0.f, 0.f);
    float4 a1 = make_float4(0.f, 0.f, 0.f, 0.f);

    #pragma unroll 4
    for (int j = 0; j < n; ++j) {
        const int   k = liv[j];
        const float s = gsc[j];
        const float4 w0 = W4[(size_t)k * 512];          // units [4t, 4t+3]
        const float4 w1 = W4[(size_t)k * 512 + 256];    // units [1024+4t, ...]
        a0.x = fmaf(s, w0.x, a0.x);
        a0.y = fmaf(s, w0.y, a0.y);
        a0.z = fmaf(s, w0.z, a0.z);
        a0.w = fmaf(s, w0.w, a0.w);
        a1.x = fmaf(s, w1.x, a1.x);
        a1.y = fmaf(s, w1.y, a1.y);
        a1.z = fmaf(s, w1.z, a1.z);
        a1.w = fmaf(s, w1.w, a1.w);
    }

    // Always store (zeros when n==0): finalize sums every KSPLIT slot.
    float4* pp = reinterpret_cast<float4*>(g_partial + (size_t)blockIdx.x * UNITS) + tid;
    pp[0]   = a0;
    pp[256] = a1;
}

// Warp-per-unit reduction of the KSPLIT partials + bias + tanh.
// Block = 256 threads = 8 warps -> 8 units per block; grid = UNITS/8 = 256.
__global__ __launch_bounds__(256) void finalize_kernel(
    const float* __restrict__ b,
    int seg_offset,
    float* __restrict__ out /* may be null */)
{
    const int warp = threadIdx.x >> 5;
    const int lane = threadIdx.x & 31;
    const int u    = blockIdx.x * 8 + warp;

    float acc = 0.0f;
    #pragma unroll
    for (int s = lane; s < KSPLIT; s += 32) {
        acc += g_partial[(size_t)s * UNITS + u];
    }
    #pragma unroll
    for (int off = 16; off > 0; off >>= 1) {
        acc += __shfl_xor_sync(0xFFFFFFFFu, acc, off);
    }

    if (lane == 0) {
        const float v = tanhf(acc + b[u]);
        g_state[seg_offset + u] = v;
        if (out) out[u] = v;
    }
}

extern "C" void kernel_launch(void* const* d_in, const int* in_sizes, int n_in,
                              void* d_out, int out_size) {
    const float* x         = (const float*)d_in[0];  // [2048] f32
    const int*   node_inds = (const int*)  d_in[1];  // [L, FANIN] i32
    const float* Ws        = (const float*)d_in[2];  // [L, FANIN, UNITS] f32
    const float* bs        = (const float*)d_in[3];  // [L, UNITS] f32
    float*       out       = (float*)d_out;          // [2048] f32

    init_kernel<<<(TOTAL + 255) / 256, 256>>>(x);

    for (int i = 0; i < L; ++i) {
        const float* Wi = Ws + (size_t)i * FANIN * UNITS;
        const int*   Ii = node_inds + i * FANIN;
        const float* bi = bs + i * UNITS;

        gemv_partial_kernel<<<KSPLIT, TPB>>>(Wi, Ii);   // 256 blocks

        const int seg = (i + 1) * UNITS;                // segment 8 exists; harmless
        finalize_kernel<<<UNITS / 8, 256>>>(bi, seg, (i == L - 1) ? out : nullptr);
    }
}

// round 7
// speedup vs baseline: 1.5089x; 1.2085x over previous
#include <cuda_runtime.h>
#include <math.h>
#include <stdint.h>

// Problem constants (match reference)
#define N_INPUTS 2048
#define UNITS    2048
#define L        8
#define FANIN    4096
#define TOTAL    (N_INPUTS + L * UNITS)   // 18432

// Persistent-kernel decomposition
#define NBLK     256                      // MUST be co-resident (>=2 blocks/SM)
#define TPB      256
#define KSPLIT   128                      // k-chunks per layer
#define KCHUNK   (FANIN / KSPLIT)         // 32 rows per chunk
#define NBAR     (2 * L)                  // grid barriers used per call

// Scratch (device globals: allocation-free per harness rules)
__device__ float g_state[TOTAL];                 // shared "outputs" vector
__device__ float g_partial[KSPLIT * UNITS];      // split-K partials (1 MB)
__device__ int   g_bar[NBAR];                    // barrier counters

// Zero state (segments 1..8 must be exact zeros for zero-skip), copy x,
// and reset the grid-barrier counters for this call.
__global__ void init_kernel(const float* __restrict__ x) {
    int i = blockIdx.x * blockDim.x + threadIdx.x;
    if (i < TOTAL) {
        g_state[i] = (i < N_INPUTS) ? x[i] : 0.0f;
    }
    if (i < NBAR) g_bar[i] = 0;
}

__device__ __forceinline__ int ldcg_i(const int* p) {
    int v;
    asm volatile("ld.global.cg.s32 %0, [%1];" : "=r"(v) : "l"(p));
    return v;
}
__device__ __forceinline__ float ldcg_f(const float* p) {
    float v;
    asm volatile("ld.global.cg.f32 %0, [%1];" : "=f"(v) : "l"(p));
    return v;
}

// Grid-wide barrier #b. All NBLK blocks are co-resident (launch_bounds
// guarantees >=2 blocks/SM -> wave 1 holds all 256 blocks), so spinning is
// deadlock-free. Release: threadfence + atomicAdd. Acquire: spin with
// L1-bypassing load, then syncthreads + threadfence (gpu-scope fence
// invalidates stale L1 lines per sm_103a CCTL.IVALL behavior).
__device__ __forceinline__ void grid_barrier(int b) {
    __syncthreads();
    if (threadIdx.x == 0) {
        __threadfence();
        atomicAdd(&g_bar[b], 1);
        while (ldcg_i(&g_bar[b]) < NBLK) {
            __nanosleep(32);
        }
    }
    __syncthreads();
    __threadfence();
}

// All 8 layers in one launch: no per-layer kernel floors.
// Block bid: kc = bid>>1 (k-chunk, 32 rows), uh = bid&1 (unit half, 1024 units).
// Zero-skip: rows whose gathered state value is exactly 0 (unwritten
// segments) are compacted away -> their 8KB W rows are never loaded.
__global__ __launch_bounds__(TPB, 2) void net_kernel(
    const float* __restrict__ Ws,        // [L, FANIN, UNITS]
    const int*   __restrict__ node_inds, // [L, FANIN]
    const float* __restrict__ bs,        // [L, UNITS]
    float*       __restrict__ out)       // [UNITS]
{
    __shared__ float gsc[KCHUNK];
    __shared__ int   liv[KCHUNK];
    __shared__ int   nliv;

    const int tid = threadIdx.x;
    const int bid = blockIdx.x;
    const int kc  = bid >> 1;
    const int uh  = bid & 1;
    const int warp = tid >> 5;
    const int lane = tid & 31;

    for (int i = 0; i < L; ++i) {
        const float* W    = Ws + (size_t)i * FANIN * UNITS;
        const int*   inds = node_inds + i * FANIN + kc * KCHUNK;

        // ---- gather + compact (zero-skip) ----
        if (tid == 0) nliv = 0;
        __syncthreads();
        if (tid < KCHUNK) {
            const float v = ldcg_f(&g_state[inds[tid]]);
            if (v != 0.0f) {
                const int j = atomicAdd(&nliv, 1);
                liv[j] = tid;
                gsc[j] = v;
            }
        }
        __syncthreads();
        const int n = nliv;

        // ---- stream live W rows, accumulate 4 units/thread ----
        // float4 row stride = UNITS/4 = 512. Thread's unit col: uh*1024+4*tid.
        const float4* W4 = reinterpret_cast<const float4*>(W)
                         + (size_t)kc * KCHUNK * 512 + uh * 256 + tid;
        float4 acc = make_float4(0.f, 0.f, 0.f, 0.f);
        #pragma unroll 4
        for (int j = 0; j < n; ++j) {
            const int   k = liv[j];
            const float s = gsc[j];
            const float4 w = W4[(size_t)k * 512];
            acc.x = fmaf(s, w.x, acc.x);
            acc.y = fmaf(s, w.y, acc.y);
            acc.z = fmaf(s, w.z, acc.z);
            acc.w = fmaf(s, w.w, acc.w);
        }
        // Always store (zeros when n==0): finalize sums every slot.
        reinterpret_cast<float4*>(g_partial + (size_t)kc * UNITS + uh * 1024)[tid] = acc;

        grid_barrier(2 * i);

        // ---- finalize: warp-per-unit over KSPLIT partials ----
        {
            const int u = bid * 8 + warp;            // 256 blocks x 8 = 2048
            float a = 0.0f;
            #pragma unroll
            for (int s = lane; s < KSPLIT; s += 32) {
                a += ldcg_f(&g_partial[(size_t)s * UNITS + u]);
            }
            #pragma unroll
            for (int off = 16; off > 0; off >>= 1) {
                a += __shfl_xor_sync(0xFFFFFFFFu, a, off);
            }
            if (lane == 0) {
                const float v = tanhf(a + bs[i * UNITS + u]);
                g_state[(i + 1) * UNITS + u] = v;    // segment 8 exists; harmless
                if (i == L - 1) out[u] = v;
            }
        }

        grid_barrier(2 * i + 1);
    }
}

extern "C" void kernel_launch(void* const* d_in, const int* in_sizes, int n_in,
                              void* d_out, int out_size) {
    const float* x         = (const float*)d_in[0];  // [2048] f32
    const int*   node_inds = (const int*)  d_in[1];  // [L, FANIN] i32
    const float* Ws        = (const float*)d_in[2];  // [L, FANIN, UNITS] f32
    const float* bs        = (const float*)d_in[3];  // [L, UNITS] f32
    float*       out       = (float*)d_out;          // [2048] f32

    init_kernel<<<(TOTAL + 255) / 256, 256>>>(x);
    net_kernel<<<NBLK, TPB>>>(Ws, node_inds, bs, out);
}

// round 8
// speedup vs baseline: 1.5440x; 1.0233x over previous
#include <cuda_runtime.h>
#include <math.h>
#include <stdint.h>

// Problem constants (match reference)
#define N_INPUTS 2048
#define UNITS    2048
#define L        8
#define FANIN    4096
#define TOTAL    (N_INPUTS + L * UNITS)   // 18432

// Persistent-kernel decomposition
#define NBLK     256                      // co-resident (>=2 blocks/SM)
#define TPB      256
#define KSPLIT   128                      // k-chunks per layer
#define KCHUNK   (FANIN / KSPLIT)         // 32 rows per chunk
#define NBAR     L                        // one grid barrier per layer

// Scratch (device globals: allocation-free per harness rules)
__device__ float g_state[TOTAL];                   // shared "outputs" vector
__device__ float g_partial[2][KSPLIT * UNITS];     // double-buffered partials
__device__ int   g_bar[NBAR];                      // barrier counters

__global__ void init_kernel(const float* __restrict__ x) {
    int i = blockIdx.x * blockDim.x + threadIdx.x;
    if (i < TOTAL) {
        g_state[i] = (i < N_INPUTS) ? x[i] : 0.0f;
    }
    if (i < NBAR) g_bar[i] = 0;
}

__device__ __forceinline__ int ldcg_i(const int* p) {
    int v; asm volatile("ld.global.cg.s32 %0, [%1];" : "=r"(v) : "l"(p)); return v;
}
__device__ __forceinline__ float ldcg_f(const float* p) {
    float v; asm volatile("ld.global.cg.f32 %0, [%1];" : "=f"(v) : "l"(p)); return v;
}

// Grid-wide barrier #b (all NBLK blocks co-resident -> deadlock-free).
__device__ __forceinline__ void grid_barrier(int b) {
    __syncthreads();
    if (threadIdx.x == 0) {
        __threadfence();
        atomicAdd(&g_bar[b], 1);
        while (ldcg_i(&g_bar[b]) < NBLK) { __nanosleep(16); }
    }
    __syncthreads();
    __threadfence();
}

// Warp-reduction of one unit's KSPLIT partials (deterministic order).
__device__ __forceinline__ float reduce_unit(const float* part, int u, int lane) {
    float a = 0.0f;
    #pragma unroll
    for (int s = lane; s < KSPLIT; s += 32) {
        a += ldcg_f(&part[(size_t)s * UNITS + u]);
    }
    #pragma unroll
    for (int off = 16; off > 0; off >>= 1) {
        a += __shfl_xor_sync(0xFFFFFFFFu, a, off);
    }
    return a;
}

// All 8 layers, ONE barrier per layer, next-layer W prefetched into L2.
// Block bid: kc = bid>>1 (k-chunk of 32 rows), uh = bid&1 (unit half).
__global__ __launch_bounds__(TPB, 2) void net_kernel(
    const float* __restrict__ Ws,        // [L, FANIN, UNITS]
    const int*   __restrict__ node_inds, // [L, FANIN]
    const float* __restrict__ bs,        // [L, UNITS]
    float*       __restrict__ out)       // [UNITS]
{
    __shared__ int   sind[KCHUNK];
    __shared__ float sval[KCHUNK];
    __shared__ float gsc[KCHUNK];
    __shared__ int   liv[KCHUNK];
    __shared__ int   nliv;

    const int tid  = threadIdx.x;
    const int bid  = blockIdx.x;
    const int kc   = bid >> 1;
    const int uh   = bid & 1;
    const int warp = tid >> 5;
    const int lane = tid & 31;
    const int myu  = bid * 8 + warp;     // this warp's finalize unit

    for (int i = 0; i < L; ++i) {
        const int* inds = node_inds + i * FANIN + kc * KCHUNK;
        const int  dlim = i * 2048;          // g_state valid below this (segs < i)
        const int  llim = dlim + 2048;       // static liveness limit
        const int  pb   = (i - 1) & 1;       // prev layer's partial buffer

        if (tid == 0) nliv = 0;
        if (tid < KCHUNK) {
            const int ind = inds[tid];
            sind[tid] = ind;
            float v = 0.0f;
            if (ind < dlim || (i == 0 && ind < llim)) v = ldcg_f(&g_state[ind]);
            sval[tid] = v;
        }
        __syncthreads();

        if (i > 0) {
            // On-the-fly values for indices in the segment being written this
            // phase (segment i): reduce prev partials directly.
            for (int k = warp; k < KCHUNK; k += 8) {
                const int ind = sind[k];
                if (ind >= dlim && ind < llim) {
                    const int u = ind - dlim;
                    const float a = reduce_unit(g_partial[pb], u, lane);
                    if (lane == 0) sval[k] = tanhf(a + bs[(i - 1) * UNITS + u]);
                }
            }
            // Finalize layer i-1 for this warp's unit -> g_state segment i
            // (consumed by layers > i after the barrier below).
            {
                const float a = reduce_unit(g_partial[pb], myu, lane);
                if (lane == 0) g_state[dlim + myu] = tanhf(a + bs[(i - 1) * UNITS + myu]);
            }
        }
        __syncthreads();

        // Compact live rows (static index test).
        if (tid < KCHUNK && sind[tid] < llim) {
            const int j = atomicAdd(&nliv, 1);
            liv[j] = tid;
            gsc[j] = sval[tid];
        }
        __syncthreads();
        const int n = nliv;

        // Prefetch NEXT layer's live rows of this block's region into L2.
        // Liveness is static (ind < (i+2)*2048). 4KB/row = 32 lines, one per lane.
        if (i + 1 < L) {
            const int* ninds = node_inds + (i + 1) * FANIN + kc * KCHUNK;
            const float* Wn = Ws + (size_t)(i + 1) * FANIN * UNITS
                            + (size_t)kc * KCHUNK * UNITS + uh * 1024;
            const int nlim = llim + 2048;
            for (int k = warp; k < KCHUNK; k += 8) {
                if (ninds[k] < nlim) {
                    const char* p = (const char*)(Wn + (size_t)k * UNITS) + lane * 128;
                    asm volatile("prefetch.global.L2 [%0];" :: "l"(p));
                }
            }
        }

        // Stream live W rows (hit L2 thanks to prev phase's prefetch).
        const float4* W4 = reinterpret_cast<const float4*>(Ws + (size_t)i * FANIN * UNITS)
                         + (size_t)kc * KCHUNK * 512 + uh * 256 + tid;
        float4 acc = make_float4(0.f, 0.f, 0.f, 0.f);
        #pragma unroll 4
        for (int j = 0; j < n; ++j) {
            const int   k = liv[j];
            const float s = gsc[j];
            const float4 w = W4[(size_t)k * 512];
            acc.x = fmaf(s, w.x, acc.x);
            acc.y = fmaf(s, w.y, acc.y);
            acc.z = fmaf(s, w.z, acc.z);
            acc.w = fmaf(s, w.w, acc.w);
        }
        reinterpret_cast<float4*>(g_partial[i & 1] + (size_t)kc * UNITS + uh * 1024)[tid] = acc;

        grid_barrier(i);
    }

    // Final output: finalize layer L-1.
    {
        const float a = reduce_unit(g_partial[(L - 1) & 1], myu, lane);
        if (lane == 0) out[myu] = tanhf(a + bs[(L - 1) * UNITS + myu]);
    }
}

extern "C" void kernel_launch(void* const* d_in, const int* in_sizes, int n_in,
                              void* d_out, int out_size) {
    const float* x         = (const float*)d_in[0];  // [2048] f32
    const int*   node_inds = (const int*)  d_in[1];  // [L, FANIN] i32
    const float* Ws        = (const float*)d_in[2];  // [L, FANIN, UNITS] f32
    const float* bs        = (const float*)d_in[3];  // [L, UNITS] f32
    float*       out       = (float*)d_out;          // [2048] f32

    init_kernel<<<(TOTAL + 255) / 256, 256>>>(x);
    net_kernel<<<NBLK, TPB>>>(Ws, node_inds, bs, out);
}

// round 9
// speedup vs baseline: 1.8539x; 1.2007x over previous
#include <cuda_runtime.h>
#include <math.h>
#include <stdint.h>

// Problem constants (match reference)
#define N_INPUTS 2048
#define UNITS    2048
#define L        8
#define FANIN    4096
#define TOTAL    (N_INPUTS + L * UNITS)   // 18432

// Persistent-kernel decomposition
#define NBLK     256                      // co-resident (>=2 blocks/SM, 148 SMs)
#define TPB      256
#define KSPLIT   128                      // k-chunks per layer
#define KCHUNK   (FANIN / KSPLIT)         // 32 rows per chunk
#define NBAR     L

// Scratch (device globals: allocation-free per harness rules)
__device__ float g_state[TOTAL];                    // shared "outputs" vector
__device__ float g_pt[2][UNITS * KSPLIT];           // TRANSPOSED partials [u][s]
__device__ int   g_bar[NBAR];

__global__ void init_kernel(const float* __restrict__ x) {
    int i = blockIdx.x * blockDim.x + threadIdx.x;
    if (i < TOTAL) g_state[i] = (i < N_INPUTS) ? x[i] : 0.0f;
    if (i < NBAR)  g_bar[i] = 0;
}

__device__ __forceinline__ float ldcg_f(const float* p) {
    float v; asm volatile("ld.global.cg.f32 %0, [%1];" : "=f"(v) : "l"(p)); return v;
}
__device__ __forceinline__ float4 ldcg_f4(const float4* p) {
    float4 v;
    asm volatile("ld.global.cg.v4.f32 {%0,%1,%2,%3}, [%4];"
                 : "=f"(v.x), "=f"(v.y), "=f"(v.z), "=f"(v.w) : "l"(p));
    return v;
}
__device__ __forceinline__ void bar_arrive(int* p) {
    asm volatile("red.release.gpu.global.add.s32 [%0], 1;" :: "l"(p) : "memory");
}
__device__ __forceinline__ int ld_acq(const int* p) {
    int v; asm volatile("ld.acquire.gpu.global.s32 %0, [%1];" : "=r"(v) : "l"(p) : "memory");
    return v;
}

// Coalesced reduction of one unit's KSPLIT partials from the transposed
// buffer: warp reads 32 consecutive float4s (512B), fixed order -> deterministic.
__device__ __forceinline__ float reduce_t(const float* buf, int u, int lane) {
    const float4 v = ldcg_f4(reinterpret_cast<const float4*>(buf) + u * (KSPLIT / 4) + lane);
    float a = (v.x + v.y) + (v.z + v.w);
    #pragma unroll
    for (int off = 16; off > 0; off >>= 1) a += __shfl_xor_sync(0xFFFFFFFFu, a, off);
    return a;
}

// Pipelined persistent kernel. Block bid: kc=bid>>1 (32-row k-chunk),
// uh=bid&1 (unit half). Per phase i:
//   finalize layer i-1 -> g_state segment i
//   deferred rows of layer i (2 newest segments) -> finish acc, store partials_i
//   ARRIVE(bar_i); bulk-stream layer i+1 rows with ind < plim (already-published
//   segments) into registers; WAIT(bar_i).
__global__ __launch_bounds__(TPB, 2) void net_kernel(
    const float* __restrict__ Ws,        // [L, FANIN, UNITS]
    const int*   __restrict__ node_inds, // [L, FANIN]
    const float* __restrict__ bs,        // [L, UNITS]
    float*       __restrict__ out)       // [UNITS]
{
    __shared__ int   sind[KCHUNK];
    __shared__ int   liv[KCHUNK];
    __shared__ float lval[KCHUNK];
    __shared__ int   nliv;

    const int tid   = threadIdx.x;
    const int bid   = blockIdx.x;
    const int kc    = bid >> 1;
    const int uh    = bid & 1;
    const int warp  = tid >> 5;
    const int lane  = tid & 31;
    const int myu   = bid * 8 + warp;        // this warp's finalize unit
    const int ubase = uh * 1024 + 4 * tid;   // this thread's 4 units

    float4 acc = make_float4(0.f, 0.f, 0.f, 0.f);
    int plim_prev = 0;                       // rows with ind < plim_prev already in acc

    for (int i = 0; i < L; ++i) {
        const int llim = (i + 1) * 2048;     // liveness limit for layer i
        const int slim = i * 2048;           // segment-i base (needs partial reduce)
        const int pb   = (i - 1) & 1;
        const int* inds = node_inds + i * FANIN + kc * KCHUNK;

        // ---- finalize layer i-1 -> g_state segment i (published at bar_i) ----
        if (i > 0) {
            const float a = reduce_t(g_pt[pb], myu, lane);
            if (lane == 0) g_state[slim + myu] = tanhf(a + bs[(i - 1) * UNITS + myu]);
        }

        // ---- deterministic compaction of deferred live rows ----
        if (warp == 0) {
            const int ind = inds[lane];
            sind[lane] = ind;
            const bool d = (ind >= plim_prev) && (ind < llim);
            const unsigned m = __ballot_sync(0xFFFFFFFFu, d);
            if (d) liv[__popc(m & ((1u << lane) - 1))] = lane;
            if (lane == 0) nliv = __popc(m);
        }
        __syncthreads();
        const int n = nliv;

        // ---- fill deferred values (g_state read or on-the-fly reduce) ----
        for (int j = warp; j < n; j += 8) {
            const int k   = liv[j];
            const int ind = sind[k];
            float v;
            if (i > 0 && ind >= slim) {
                const int u = ind - slim;
                const float a = reduce_t(g_pt[pb], u, lane);
                v = tanhf(a + bs[(i - 1) * UNITS + u]);
            } else {
                v = (lane == 0) ? ldcg_f(&g_state[ind]) : 0.0f;
            }
            if (lane == 0) lval[j] = v;
        }
        __syncthreads();

        // ---- stream deferred W rows, finish acc ----
        const float4* W4 = reinterpret_cast<const float4*>(Ws + (size_t)i * FANIN * UNITS)
                         + (size_t)kc * KCHUNK * 512 + uh * 256 + tid;
        #pragma unroll 4
        for (int j = 0; j < n; ++j) {
            const int   k = liv[j];
            const float s = lval[j];
            const float4 w = W4[(size_t)k * 512];
            acc.x = fmaf(s, w.x, acc.x);
            acc.y = fmaf(s, w.y, acc.y);
            acc.z = fmaf(s, w.z, acc.z);
            acc.w = fmaf(s, w.w, acc.w);
        }

        // ---- store transposed partials for layer i ----
        float* pt = g_pt[i & 1];
        pt[(size_t)(ubase + 0) * KSPLIT + kc] = acc.x;
        pt[(size_t)(ubase + 1) * KSPLIT + kc] = acc.y;
        pt[(size_t)(ubase + 2) * KSPLIT + kc] = acc.z;
        pt[(size_t)(ubase + 3) * KSPLIT + kc] = acc.w;
        __syncthreads();

        if (tid == 0) bar_arrive(&g_bar[i]);

        // ---- bulk pre-stream of layer i+1 (overlaps barrier skew) ----
        // Segments [0, plim) are globally published at this point.
        const int plim = (i == 0) ? 2048 : slim;
        float4 nacc = make_float4(0.f, 0.f, 0.f, 0.f);
        if (i + 1 < L) {
            const int* ninds = node_inds + (i + 1) * FANIN + kc * KCHUNK;
            if (warp == 0) {
                const int ind = ninds[lane];
                sind[lane] = ind;
                const bool p = (ind < plim);
                const unsigned m = __ballot_sync(0xFFFFFFFFu, p);
                if (p) liv[__popc(m & ((1u << lane) - 1))] = lane;
                if (lane == 0) nliv = __popc(m);
            }
            __syncthreads();
            const int n2 = nliv;
            if (tid < KCHUNK && tid < n2) {
                lval[tid] = ldcg_f(&g_state[sind[liv[tid]]]);
            }
            __syncthreads();

            const float4* W4n = reinterpret_cast<const float4*>(
                                    Ws + (size_t)(i + 1) * FANIN * UNITS)
                              + (size_t)kc * KCHUNK * 512 + uh * 256 + tid;
            #pragma unroll 4
            for (int j = 0; j < n2; ++j) {
                const int   k = liv[j];
                const float s = lval[j];
                const float4 w = W4n[(size_t)k * 512];
                nacc.x = fmaf(s, w.x, nacc.x);
                nacc.y = fmaf(s, w.y, nacc.y);
                nacc.z = fmaf(s, w.z, nacc.z);
                nacc.w = fmaf(s, w.w, nacc.w);
            }
        }

        // ---- wait for all blocks (partials_i + segment i published) ----
        if (tid == 0) {
            while (ld_acq(&g_bar[i]) < NBLK) { __nanosleep(16); }
        }
        __syncthreads();

        acc = nacc;
        plim_prev = plim;
    }

    // ---- final output: finalize layer L-1 ----
    {
        const float a = reduce_t(g_pt[(L - 1) & 1], myu, lane);
        if (lane == 0) out[myu] = tanhf(a + bs[(L - 1) * UNITS + myu]);
    }
}

extern "C" void kernel_launch(void* const* d_in, const int* in_sizes, int n_in,
                              void* d_out, int out_size) {
    const float* x         = (const float*)d_in[0];  // [2048] f32
    const int*   node_inds = (const int*)  d_in[1];  // [L, FANIN] i32
    const float* Ws        = (const float*)d_in[2];  // [L, FANIN, UNITS] f32
    const float* bs        = (const float*)d_in[3];  // [L, UNITS] f32
    float*       out       = (float*)d_out;          // [2048] f32

    init_kernel<<<(TOTAL + 255) / 256, 256>>>(x);
    net_kernel<<<NBLK, TPB>>>(Ws, node_inds, bs, out);
}

// round 10
// speedup vs baseline: 1.9619x; 1.0583x over previous
#include <cuda_runtime.h>
#include <math.h>
#include <stdint.h>

// Problem constants (match reference)
#define N_INPUTS 2048
#define UNITS    2048
#define L        8
#define FANIN    4096
#define TOTAL    (N_INPUTS + L * UNITS)   // 18432

// Persistent-kernel decomposition
#define NBLK     256                      // co-resident (>=2 blocks/SM, 148 SMs)
#define TPB      256
#define KSPLIT   128                      // k-chunks per layer
#define KCHUNK   (FANIN / KSPLIT)         // 32 rows per chunk
#define NBAR     L

// Scratch (device globals: allocation-free per harness rules)
__device__ float g_state[TOTAL];                    // shared "outputs" vector
__device__ float g_pt[2][UNITS * KSPLIT];           // TRANSPOSED partials [u][s]
__device__ int   g_bar[NBAR];

__global__ void init_kernel(const float* __restrict__ x) {
    int i = blockIdx.x * blockDim.x + threadIdx.x;
    if (i < TOTAL) g_state[i] = (i < N_INPUTS) ? x[i] : 0.0f;
    if (i < NBAR)  g_bar[i] = 0;
}

__device__ __forceinline__ float ldcg_f(const float* p) {
    float v; asm volatile("ld.global.cg.f32 %0, [%1];" : "=f"(v) : "l"(p)); return v;
}
__device__ __forceinline__ float4 ldcg_f4(const float4* p) {
    float4 v;
    asm volatile("ld.global.cg.v4.f32 {%0,%1,%2,%3}, [%4];"
                 : "=f"(v.x), "=f"(v.y), "=f"(v.z), "=f"(v.w) : "l"(p));
    return v;
}
__device__ __forceinline__ void bar_arrive(int* p) {
    asm volatile("red.release.gpu.global.add.s32 [%0], 1;" :: "l"(p) : "memory");
}
__device__ __forceinline__ int ld_acq(const int* p) {
    int v; asm volatile("ld.acquire.gpu.global.s32 %0, [%1];" : "=r"(v) : "l"(p) : "memory");
    return v;
}
__device__ __forceinline__ void pf_l2(const void* p) {
    asm volatile("prefetch.global.L2 [%0];" :: "l"(p));
}

// Coalesced reduction of one unit's KSPLIT partials from the transposed
// buffer: warp reads 32 consecutive float4s (512B), fixed order -> deterministic.
__device__ __forceinline__ float reduce_t(const float* buf, int u, int lane) {
    const float4 v = ldcg_f4(reinterpret_cast<const float4*>(buf) + u * (KSPLIT / 4) + lane);
    float a = (v.x + v.y) + (v.z + v.w);
    #pragma unroll
    for (int off = 16; off > 0; off >>= 1) a += __shfl_xor_sync(0xFFFFFFFFu, a, off);
    return a;
}

// Pipelined persistent kernel. Block bid: kc=bid>>1 (32-row k-chunk),
// uh=bid&1 (unit half). Per phase i:
//   finalize layer i-1 -> g_state segment i
//   deferred rows of layer i (W already L2-prefetched last phase) -> finish acc
//   store transposed partials_i; ARRIVE(bar_i)
//   prefetch layer i+1's deferred W rows to L2; bulk-stream layer i+1's
//   already-published rows into registers; WAIT(bar_i).
__global__ __launch_bounds__(TPB, 2) void net_kernel(
    const float* __restrict__ Ws,        // [L, FANIN, UNITS]
    const int*   __restrict__ node_inds, // [L, FANIN]
    const float* __restrict__ bs,        // [L, UNITS]
    float*       __restrict__ out)       // [UNITS]
{
    __shared__ int   sind[KCHUNK];
    __shared__ int   liv[KCHUNK];      // bulk list (overlap) / deferred list (serial)
    __shared__ int   dliv[KCHUNK];     // deferred list built in overlap window
    __shared__ float lval[KCHUNK];
    __shared__ int   nliv, ndef;

    const int tid   = threadIdx.x;
    const int bid   = blockIdx.x;
    const int kc    = bid >> 1;
    const int uh    = bid & 1;
    const int warp  = tid >> 5;
    const int lane  = tid & 31;
    const int myu   = bid * 8 + warp;        // this warp's finalize unit
    const int ubase = uh * 1024 + 4 * tid;   // this thread's 4 units

    float4 acc = make_float4(0.f, 0.f, 0.f, 0.f);
    int plim_prev = 0;                       // rows with ind < plim_prev already in acc

    for (int i = 0; i < L; ++i) {
        const int llim = (i + 1) * 2048;     // liveness limit for layer i
        const int slim = i * 2048;           // segment-i base (needs partial reduce)
        const int pb   = (i - 1) & 1;
        const int* inds = node_inds + i * FANIN + kc * KCHUNK;

        // ---- finalize layer i-1 -> g_state segment i (published at bar_i) ----
        if (i > 0) {
            const float a = reduce_t(g_pt[pb], myu, lane);
            if (lane == 0) g_state[slim + myu] = tanhf(a + bs[(i - 1) * UNITS + myu]);
        }

        // ---- deterministic compaction of deferred live rows ----
        if (warp == 0) {
            const int ind = inds[lane];
            sind[lane] = ind;
            const bool d = (ind >= plim_prev) && (ind < llim);
            const unsigned m = __ballot_sync(0xFFFFFFFFu, d);
            if (d) liv[__popc(m & ((1u << lane) - 1))] = lane;
            if (lane == 0) nliv = __popc(m);
        }
        __syncthreads();
        const int n = nliv;

        // ---- fill deferred values (g_state read or on-the-fly reduce) ----
        for (int j = warp; j < n; j += 8) {
            const int k   = liv[j];
            const int ind = sind[k];
            float v;
            if (i > 0 && ind >= slim) {
                const int u = ind - slim;
                const float a = reduce_t(g_pt[pb], u, lane);
                v = tanhf(a + bs[(i - 1) * UNITS + u]);
            } else {
                v = (lane == 0) ? ldcg_f(&g_state[ind]) : 0.0f;
            }
            if (lane == 0) lval[j] = v;
        }
        __syncthreads();

        // ---- stream deferred W rows (L2-hot from last phase's prefetch) ----
        const float4* W4 = reinterpret_cast<const float4*>(Ws + (size_t)i * FANIN * UNITS)
                         + (size_t)kc * KCHUNK * 512 + uh * 256 + tid;
        #pragma unroll 4
        for (int j = 0; j < n; ++j) {
            const int   k = liv[j];
            const float s = lval[j];
            const float4 w = W4[(size_t)k * 512];
            acc.x = fmaf(s, w.x, acc.x);
            acc.y = fmaf(s, w.y, acc.y);
            acc.z = fmaf(s, w.z, acc.z);
            acc.w = fmaf(s, w.w, acc.w);
        }

        // ---- store transposed partials for layer i ----
        float* pt = g_pt[i & 1];
        pt[(size_t)(ubase + 0) * KSPLIT + kc] = acc.x;
        pt[(size_t)(ubase + 1) * KSPLIT + kc] = acc.y;
        pt[(size_t)(ubase + 2) * KSPLIT + kc] = acc.z;
        pt[(size_t)(ubase + 3) * KSPLIT + kc] = acc.w;
        __syncthreads();

        if (tid == 0) bar_arrive(&g_bar[i]);

        // ---- overlap window: prefetch deferred W + bulk-stream layer i+1 ----
        // Segments [0, plim) are globally published at this point.
        const int plim = (i == 0) ? 2048 : slim;
        float4 nacc = make_float4(0.f, 0.f, 0.f, 0.f);
        if (i + 1 < L) {
            const int nlim = llim + 2048;    // liveness limit for layer i+1
            const int* ninds = node_inds + (i + 1) * FANIN + kc * KCHUNK;
            if (warp == 0) {
                const int ind = ninds[lane];
                sind[lane] = ind;
                const bool lv = (ind < nlim);
                const bool p  = (ind < plim);
                const unsigned mb = __ballot_sync(0xFFFFFFFFu, p);
                const unsigned md = __ballot_sync(0xFFFFFFFFu, lv && !p);
                if (p)        liv [__popc(mb & ((1u << lane) - 1))] = lane;
                if (lv && !p) dliv[__popc(md & ((1u << lane) - 1))] = lane;
                if (lane == 0) { nliv = __popc(mb); ndef = __popc(md); }
            }
            __syncthreads();
            const int n2 = nliv;
            const int nd = ndef;

            // Prefetch deferred W rows of layer i+1 into L2 FIRST: the fetch
            // overlaps the bulk stream below and next phase's serial window
            // then reads them at L2 latency.
            const float* Wn = Ws + (size_t)(i + 1) * FANIN * UNITS
                            + (size_t)kc * KCHUNK * UNITS + uh * 1024;
            for (int j = warp; j < nd; j += 8) {
                const char* p = (const char*)(Wn + (size_t)dliv[j] * UNITS) + lane * 128;
                pf_l2(p);
            }

            if (tid < KCHUNK && tid < n2) {
                lval[tid] = ldcg_f(&g_state[sind[liv[tid]]]);
            }
            __syncthreads();

            const float4* W4n = reinterpret_cast<const float4*>(
                                    Ws + (size_t)(i + 1) * FANIN * UNITS)
                              + (size_t)kc * KCHUNK * 512 + uh * 256 + tid;
            #pragma unroll 4
            for (int j = 0; j < n2; ++j) {
                const int   k = liv[j];
                const float s = lval[j];
                const float4 w = W4n[(size_t)k * 512];
                nacc.x = fmaf(s, w.x, nacc.x);
                nacc.y = fmaf(s, w.y, nacc.y);
                nacc.z = fmaf(s, w.z, nacc.z);
                nacc.w = fmaf(s, w.w, nacc.w);
            }
        }

        // ---- wait for all blocks (partials_i + segment i published) ----
        if (tid == 0) {
            while (ld_acq(&g_bar[i]) < NBLK) { __nanosleep(16); }
        }
        __syncthreads();

        acc = nacc;
        plim_prev = plim;
    }

    // ---- final output: finalize layer L-1 ----
    {
        const float a = reduce_t(g_pt[(L - 1) & 1], myu, lane);
        if (lane == 0) out[myu] = tanhf(a + bs[(L - 1) * UNITS + myu]);
    }
}

extern "C" void kernel_launch(void* const* d_in, const int* in_sizes, int n_in,
                              void* d_out, int out_size) {
    const float* x         = (const float*)d_in[0];  // [2048] f32
    const int*   node_inds = (const int*)  d_in[1];  // [L, FANIN] i32
    const float* Ws        = (const float*)d_in[2];  // [L, FANIN, UNITS] f32
    const float* bs        = (const float*)d_in[3];  // [L, UNITS] f32
    float*       out       = (float*)d_out;          // [2048] f32

    init_kernel<<<(TOTAL + 255) / 256, 256>>>(x);
    net_kernel<<<NBLK, TPB>>>(Ws, node_inds, bs, out);
}